// round 10
// baseline (speedup 1.0000x reference)
#include <cuda_runtime.h>
#include <cstdint>

#define NODES 336
#define NPC   8192
#define NUMCASE 2048
#define CPB 2
#define GRID (NUMCASE / CPB)        // 1024 -> single wave at ~7 CTAs/SM
#define MIU_F 1.9e-05f
#define ALPHA_F 0.10471975511965977f
#define QCOEF_F 73830.75f           // 0.5*1.225*ACOUSTIC^2
#define FULL 0xffffffffu

#define CRD_BYTES (2 * NODES * 2 * 4)   // 5376 (n0 + n1 rows)
#define F1_BYTES  (NODES * 4 * 4)       // 5376 (f1 rows only)
#define TOT_BYTES (CRD_BYTES + F1_BYTES)

__device__ __forceinline__ uint32_t smem_u32(const void* p) {
    return (uint32_t)__cvta_generic_to_shared(p);
}

__global__ __launch_bounds__(128, 7) void dyn_kernel(
    const float* __restrict__ coords,
    const float* __restrict__ fields,
    const float* __restrict__ design,
    float2* __restrict__ out)
{
    const int c0 = blockIdx.x * CPB;
    const int t = threadIdx.x;

    __shared__ alignas(16) float2 s_crd[2][2 * NODES];
    __shared__ alignas(16) float4 s_f1[2][NODES];
    __shared__ alignas(8)  uint64_t mbar[2];
    __shared__ float s_red[4][8];

    if (t == 0) {
        asm volatile("mbarrier.init.shared.b64 [%0], 1;" :: "r"(smem_u32(&mbar[0])) : "memory");
        asm volatile("mbarrier.init.shared.b64 [%0], 1;" :: "r"(smem_u32(&mbar[1])) : "memory");
    }
    __syncthreads();

    // ---- t0: launch TMA bulk copies for BOTH cases immediately ----
    if (t == 0) {
        #pragma unroll
        for (int st = 0; st < 2; st++) {
            uint32_t mb = smem_u32(&mbar[st]);
            const int base = (c0 + st) * NPC;
            asm volatile("mbarrier.arrive.expect_tx.shared.b64 _, [%0], %1;" ::
                         "r"(mb), "r"((uint32_t)TOT_BYTES) : "memory");
            const char* g_crd = (const char*)(coords + (size_t)base * 2);
            const char* g_f1  = (const char*)(fields + (size_t)(base + NODES) * 4);
            asm volatile("cp.async.bulk.shared::cta.global.mbarrier::complete_tx::bytes [%0], [%1], %2, [%3];"
                         :: "r"(smem_u32(s_crd[st])), "l"(g_crd), "r"((uint32_t)CRD_BYTES), "r"(mb) : "memory");
            asm volatile("cp.async.bulk.shared::cta.global.mbarrier::complete_tx::bytes [%0], [%1], %2, [%3];"
                         :: "r"(smem_u32(s_f1[st])), "l"(g_f1), "r"((uint32_t)F1_BYTES), "r"(mb) : "memory");
        }
    }

    // ---- all threads: concurrent scalar gathers on the LDG path ----
    float pt[2][3];
    float d3[2] = {0.f, 0.f}, d4[2] = {0.f, 0.f};
    #pragma unroll
    for (int cc = 0; cc < 2; cc++) {
        const int base = (c0 + cc) * NPC;
        #pragma unroll
        for (int k = 0; k < 3; k++) {
            int j = t + k * 128;
            bool valid = (k < 2) || (t < NODES - 256);
            if (valid) {
                pt[cc][k] = fields[4 * (base + j)];        // f0[:, :, 0]
                d3[cc] += design[5 * (base + j) + 3];
                d4[cc] += design[5 * (base + j) + 4];
            }
        }
    }

    // ---- per-case: wait TMA stage, compute, reduce ----
    #pragma unroll
    for (int cc = 0; cc < 2; cc++) {
        {
            uint32_t mb = smem_u32(&mbar[cc]);
            uint32_t done;
            asm volatile(
                "{\n\t.reg .pred p;\n\t"
                "mbarrier.try_wait.parity.acquire.cta.shared::cta.b64 p, [%1], 0;\n\t"
                "selp.b32 %0, 1, 0, p;\n\t}"
                : "=r"(done) : "r"(mb) : "memory");
            while (!done) {
                asm volatile(
                    "{\n\t.reg .pred p;\n\t"
                    "mbarrier.try_wait.parity.acquire.cta.shared::cta.b64 p, [%1], 0, 0x989680;\n\t"
                    "selp.b32 %0, 1, 0, p;\n\t}"
                    : "=r"(done) : "r"(mb) : "memory");
            }
        }

        float Fx = 0.f, Fy = 0.f;
        #pragma unroll
        for (int k = 0; k < 3; k++) {
            int j = t + k * 128;
            bool valid = (k < 2) || (t < NODES - 256);
            if (valid) {
                int jp  = (j + 1 == NODES) ? 0 : j + 1;
                int jpp = (jp + 1 == NODES) ? 0 : jp + 1;
                float2 a  = s_crd[cc][j];
                float2 b  = s_crd[cc][jp];
                float2 cn = s_crd[cc][jpp];
                float2 a1 = s_crd[cc][NODES + j];
                float2 b1 = s_crd[cc][NODES + jp];
                float4 f1  = s_f1[cc][j];
                float4 f1p = s_f1[cc][jp];

                float tx = b.x - a.x, ty = b.y - a.y;
                float tn = sqrtf(tx * tx + ty * ty);
                float dx = a1.x - a.x, dy = a1.y - a.y;
                float dl = sqrtf(dx * dx + dy * dy);
                float tau0 = MIU_F * ((f1.z * tx + f1.w * ty) / tn) / dl;

                float tx1 = cn.x - b.x, ty1 = cn.y - b.y;
                float tn1 = sqrtf(tx1 * tx1 + ty1 * ty1);
                float dx1 = b1.x - b.x, dy1 = b1.y - b.y;
                float dl1 = sqrtf(dx1 * dx1 + dy1 * dy1);
                float tau1 = MIU_F * ((f1p.z * tx1 + f1p.w * ty1) / tn1) / dl1;

                float ta = 0.5f * (tau0 + tau1);
                // -Px = -pt*T.y ; -Py = +pt*T.x ; +50*tau_ave*T
                Fx += -pt[cc][k] * ty + 50.f * ta * tx;
                Fy +=  pt[cc][k] * tx + 50.f * ta * ty;
            }
        }

        float r3 = d3[cc], r4 = d4[cc];
        #pragma unroll
        for (int off = 16; off; off >>= 1) {
            Fx += __shfl_down_sync(FULL, Fx, off);
            Fy += __shfl_down_sync(FULL, Fy, off);
            r3 += __shfl_down_sync(FULL, r3, off);
            r4 += __shfl_down_sync(FULL, r4, off);
        }
        int warp = t >> 5, lane = t & 31;
        if (lane == 0) {
            s_red[warp][4 * cc + 0] = Fx;
            s_red[warp][4 * cc + 1] = Fy;
            s_red[warp][4 * cc + 2] = r3;
            s_red[warp][4 * cc + 3] = r4;
        }
    }
    __syncthreads();

    // ---- epilogue: threads 0,1 finalize cases ----
    if (t < 2) {
        float fx = 0.f, fy = 0.f, s3 = 0.f, s4 = 0.f;
        #pragma unroll
        for (int w = 0; w < 4; w++) {
            fx += s_red[w][4 * t + 0];
            fy += s_red[w][4 * t + 1];
            s3 += s_red[w][4 * t + 2];
            s4 += s_red[w][4 * t + 3];
        }
        float Ma = s3 * (0.3f / (float)NODES) + 0.3f;
        float af = s4 * (ALPHA_F / (float)NODES);
        float ca = cosf(af), sa = sinf(af);
        float Fxn = fx * ca + fy * sa;
        float Fyn = fy * ca - Fxn * sa;   // reference uses Fx_new here (literal)
        float q = QCOEF_F * Ma * Ma;
        out[c0 + t] = make_float2(Fxn / q, Fyn / q);
    }
}

extern "C" void kernel_launch(void* const* d_in, const int* in_sizes, int n_in,
                              void* d_out, int out_size) {
    // metadata order: batch(int32), coords(f32), fields(f32), design(f32), num_case, nodes_num
    const float* coords = (const float*)d_in[1];
    const float* fields = (const float*)d_in[2];
    const float* design = (const float*)d_in[3];
    float2* out = (float2*)d_out;
    dyn_kernel<<<GRID, 128>>>(coords, fields, design, out);
}

// round 11
// speedup vs baseline: 1.1866x; 1.1866x over previous
#include <cuda_runtime.h>

#define NODES 336
#define NPC   8192
#define NUMCASE 2048
#define MIU_F 1.9e-05f
#define ALPHA_F 0.10471975511965977f   // 6*pi/180
#define QCOEF_F 73830.75f              // 0.5*1.225*ACOUSTIC^2
#define FULL 0xffffffffu

// 2048 CTAs x 64 threads: ALL CTAs resident simultaneously (13.8/SM, 27.7 warps/SM),
// single wave, zero CTA turnover. Thread t owns nodes t+64k, k=0..5 (k=5: t<16).
__global__ __launch_bounds__(64) void dyn_kernel(
    const float* __restrict__ coords,
    const float* __restrict__ fields,
    const float* __restrict__ design,
    float2* __restrict__ out)
{
    const int c = blockIdx.x;
    const int base = c * NPC;
    const int t = threadIdx.x;

    __shared__ float2 s_n0[NODES];
    __shared__ float2 s_f1[NODES];   // (u, v)
    __shared__ float  s_rdl[NODES];  // 1/delta
    __shared__ float  s_red[2][4];

    float2 n0[6];
    float pt[6];
    float d3 = 0.f, d4 = 0.f;

    const float2* cf2 = (const float2*)coords;
    const float4* ff4 = (const float4*)fields;

    // ---- Phase 0: front-batched loads (up to 36 independent LDGs/thread) ----
    #pragma unroll
    for (int k = 0; k < 6; k++) {
        int j = t + k * 64;
        bool valid = (k < 5) || (t < NODES - 320);
        if (valid) {
            float2 a = cf2[base + j];
            float2 b = cf2[base + NODES + j];
            float4 f1 = ff4[base + NODES + j];
            n0[k] = a;
            pt[k] = fields[4 * (base + j)];          // f0[:, :, 0]
            d3 += design[5 * (base + j) + 3];
            d4 += design[5 * (base + j) + 4];
            s_n0[j] = a;
            s_f1[j] = make_float2(f1.z, f1.w);
            float dx = b.x - a.x, dy = b.y - a.y;
            s_rdl[j] = rsqrtf(dx * dx + dy * dy);    // 1/delta
        }
    }
    __syncthreads();

    // ---- Phase 1: tau[j], tau[j+1] via rsqrt products; accumulate forces ----
    float Fx = 0.f, Fy = 0.f;
    #pragma unroll
    for (int k = 0; k < 6; k++) {
        int j = t + k * 64;
        bool valid = (k < 5) || (t < NODES - 320);
        if (valid) {
            int jp  = (j + 1 == NODES) ? 0 : j + 1;
            int jpp = (jp + 1 == NODES) ? 0 : jp + 1;
            float2 a  = n0[k];
            float2 b  = s_n0[jp];
            float2 cn = s_n0[jpp];
            float2 f  = s_f1[j];
            float2 fn = s_f1[jp];

            float tx = b.x - a.x, ty = b.y - a.y;
            // tau0 = MIU * (f.T)/|T| / delta  = MIU * (f.T) * rsqrt(|T|^2) * (1/delta)
            float tau0 = MIU_F * (f.x * tx + f.y * ty)
                         * rsqrtf(tx * tx + ty * ty) * s_rdl[j];
            float tx1 = cn.x - b.x, ty1 = cn.y - b.y;
            float tau1 = MIU_F * (fn.x * tx1 + fn.y * ty1)
                         * rsqrtf(tx1 * tx1 + ty1 * ty1) * s_rdl[jp];

            float ta = 0.5f * (tau0 + tau1);
            // -Px = -pt*T.y ; -Py = +pt*T.x ; +50*tau_ave*T
            Fx += -pt[k] * ty + 50.f * ta * tx;
            Fy +=  pt[k] * tx + 50.f * ta * ty;
        }
    }

    // ---- Reduction: 2 warps ----
    #pragma unroll
    for (int off = 16; off; off >>= 1) {
        Fx += __shfl_down_sync(FULL, Fx, off);
        Fy += __shfl_down_sync(FULL, Fy, off);
        d3 += __shfl_down_sync(FULL, d3, off);
        d4 += __shfl_down_sync(FULL, d4, off);
    }
    int warp = t >> 5, lane = t & 31;
    if (lane == 0) {
        s_red[warp][0] = Fx;
        s_red[warp][1] = Fy;
        s_red[warp][2] = d3;
        s_red[warp][3] = d4;
    }
    __syncthreads();

    if (t == 0) {
        float fx = s_red[0][0] + s_red[1][0];
        float fy = s_red[0][1] + s_red[1][1];
        float s3 = s_red[0][2] + s_red[1][2];
        float s4 = s_red[0][3] + s_red[1][3];
        float Ma = s3 * (0.3f / (float)NODES) + 0.3f;
        float af = s4 * (ALPHA_F / (float)NODES);
        float ca = cosf(af), sa = sinf(af);
        float Fxn = fx * ca + fy * sa;
        float Fyn = fy * ca - Fxn * sa;   // reference uses Fx_new here (literal)
        float q = QCOEF_F * Ma * Ma;
        out[c] = make_float2(Fxn / q, Fyn / q);
    }
}

extern "C" void kernel_launch(void* const* d_in, const int* in_sizes, int n_in,
                              void* d_out, int out_size) {
    // metadata order: batch(int32), coords(f32), fields(f32), design(f32), num_case, nodes_num
    const float* coords = (const float*)d_in[1];
    const float* fields = (const float*)d_in[2];
    const float* design = (const float*)d_in[3];
    float2* out = (float2*)d_out;
    dyn_kernel<<<NUMCASE, 64>>>(coords, fields, design, out);
}

// round 12
// speedup vs baseline: 1.4963x; 1.2610x over previous
#include <cuda_runtime.h>

#define NODES 336
#define NPC   8192
#define NUMCASE 2048
#define MIU_F 1.9e-05f
#define ALPHA_F 0.10471975511965977f   // 6*pi/180
#define QCOEF_F 73830.75f              // 0.5*1.225*ACOUSTIC^2
#define FULL 0xffffffffu

// Key insight: the SFU (MUFU) pipe was the hidden bottleneck (~3 rsqrt-class
// ops/node = 14.7us of SFU time chip-wide). This version uses exactly ONE
// MUFU per node: tau = MIU*(f.T)*rsqrt(|T|^2 * |delta|^2), computed once and
// shared through smem.
__global__ __launch_bounds__(128, 12) void dyn_kernel(
    const float* __restrict__ coords,
    const float* __restrict__ fields,
    const float* __restrict__ design,
    float2* __restrict__ out)
{
    const int c = blockIdx.x;
    const int base = c * NPC;
    const int t = threadIdx.x;

    __shared__ float2 s_n0[NODES];
    __shared__ float  s_tau[NODES];
    __shared__ float  s_red[4][4];

    // thread t handles nodes t, t+128, t+256 (last only for t<80)
    float2 n0[3], n1[3];
    float f1u[3], f1v[3], pt[3];
    float d3 = 0.f, d4 = 0.f;

    const float2* cf2 = (const float2*)coords;
    const float4* ff4 = (const float4*)fields;

    // ---- Phase 0: front-batched loads ----
    #pragma unroll
    for (int k = 0; k < 3; k++) {
        int j = t + k * 128;
        bool valid = (k < 2) || (t < NODES - 256);
        if (valid) {
            n0[k] = cf2[base + j];
            n1[k] = cf2[base + NODES + j];
            float4 f1 = ff4[base + NODES + j];
            f1u[k] = f1.z;
            f1v[k] = f1.w;
            pt[k]  = fields[4 * (base + j)];          // f0[:, :, 0]
            d3 += design[5 * (base + j) + 3];
            d4 += design[5 * (base + j) + 4];
            s_n0[j] = n0[k];
        }
    }
    __syncthreads();

    // ---- Phase 1: tau once per node, ONE fused MUFU ----
    float Tx[3], Ty[3];
    #pragma unroll
    for (int k = 0; k < 3; k++) {
        int j = t + k * 128;
        bool valid = (k < 2) || (t < NODES - 256);
        if (valid) {
            int jp = (j + 1 == NODES) ? 0 : j + 1;
            float2 np = s_n0[jp];
            float tx = np.x - n0[k].x, ty = np.y - n0[k].y;
            Tx[k] = tx; Ty[k] = ty;
            float tn2 = tx * tx + ty * ty;
            float dx = n1[k].x - n0[k].x, dy = n1[k].y - n0[k].y;
            float dl2 = dx * dx + dy * dy;
            // tau = MIU * (f.T)/|T|/|d| = MIU*(f.T)*rsqrt(tn2*dl2)
            s_tau[j] = MIU_F * (f1u[k] * tx + f1v[k] * ty) * rsqrtf(tn2 * dl2);
        }
    }
    __syncthreads();

    // ---- Phase 2: forces (no MUFU) ----
    float Fx = 0.f, Fy = 0.f;
    #pragma unroll
    for (int k = 0; k < 3; k++) {
        int j = t + k * 128;
        bool valid = (k < 2) || (t < NODES - 256);
        if (valid) {
            int jp = (j + 1 == NODES) ? 0 : j + 1;
            float tau_ave = 0.5f * (s_tau[j] + s_tau[jp]);
            // -Px = -pt*T.y ; -Py = +pt*T.x ; +50*tau_ave*T
            Fx += -pt[k] * Ty[k] + 50.f * tau_ave * Tx[k];
            Fy +=  pt[k] * Tx[k] + 50.f * tau_ave * Ty[k];
        }
    }

    // ---- Block reduction over 4 warps ----
    #pragma unroll
    for (int off = 16; off; off >>= 1) {
        Fx += __shfl_down_sync(FULL, Fx, off);
        Fy += __shfl_down_sync(FULL, Fy, off);
        d3 += __shfl_down_sync(FULL, d3, off);
        d4 += __shfl_down_sync(FULL, d4, off);
    }
    int warp = t >> 5, lane = t & 31;
    if (lane == 0) {
        s_red[warp][0] = Fx;
        s_red[warp][1] = Fy;
        s_red[warp][2] = d3;
        s_red[warp][3] = d4;
    }
    __syncthreads();

    if (t == 0) {
        float fx = 0.f, fy = 0.f, s3 = 0.f, s4 = 0.f;
        #pragma unroll
        for (int w = 0; w < 4; w++) {
            fx += s_red[w][0];
            fy += s_red[w][1];
            s3 += s_red[w][2];
            s4 += s_red[w][3];
        }
        float Ma = s3 * (0.3f / (float)NODES) + 0.3f;
        float af = s4 * (ALPHA_F / (float)NODES);
        float ca = cosf(af), sa = sinf(af);
        float Fxn = fx * ca + fy * sa;
        float Fyn = fy * ca - Fxn * sa;   // reference uses Fx_new here (literal)
        float q = QCOEF_F * Ma * Ma;
        out[c] = make_float2(Fxn / q, Fyn / q);
    }
}

extern "C" void kernel_launch(void* const* d_in, const int* in_sizes, int n_in,
                              void* d_out, int out_size) {
    // metadata order: batch(int32), coords(f32), fields(f32), design(f32), num_case, nodes_num
    const float* coords = (const float*)d_in[1];
    const float* fields = (const float*)d_in[2];
    const float* design = (const float*)d_in[3];
    float2* out = (float2*)d_out;
    dyn_kernel<<<NUMCASE, 128>>>(coords, fields, design, out);
}